// round 2
// baseline (speedup 1.0000x reference)
#include <cuda_runtime.h>
#include <math.h>

#define D 1024
#define TB 4096
#define BATCH 16
// spatial = TB/BATCH = 256

// ---------------- device scratch (static globals; no allocation) ----------------
__device__ float2 g_SA  [D*D];
__device__ float2 g_SP  [D*D];
__device__ float2 g_SP2 [D*D];
__device__ float2 g_ACCa[D*D];
__device__ float2 g_ACCb[D*D];
__device__ float2 g_U   [D*D];
__device__ float2 g_V   [D*D];
__device__ float2 g_M   [D*D];
__device__ float2 g_Minv[D*D];
__device__ float2 g_W   [D*2*D];    // row i: [0:D)=W1[i,:], [D:2D)=W2[i,:]
__device__ float2 g_HX  [TB*2*D];   // packed [h|x] complex
__device__ float2 g_C   [TB*D];
__device__ float2 g_s   [D];
__device__ float2 g_sinv[D];
__device__ float2 g_opd [D];
__device__ float2 g_opf [D];
__device__ float  g_xm  [BATCH*2*D];
__device__ float  g_fre [BATCH*D];
__device__ float  g_fim [BATCH*D];
__device__ float  g_proj[BATCH*2*D];
__device__ float2 g_S2  [BATCH*D];
__device__ float2 g_t   [BATCH*D];

__device__ __forceinline__ float2 cmulf(float2 a, float2 b) {
    return make_float2(fmaf(a.x, b.x, -a.y * b.y), fmaf(a.x, b.y, a.y * b.x));
}

// ---------------- elementwise / small kernels ----------------

// A = 0.5(re - re^T) + i*0.5(im + im^T)
__global__ void k_buildA(float2* __restrict__ A, const float* __restrict__ re,
                         const float* __restrict__ im) {
    int idx = blockIdx.x * 256 + threadIdx.x;
    int i = idx >> 10, j = idx & (D - 1);
    A[idx] = make_float2(0.5f * (re[i * D + j] - re[j * D + i]),
                         0.5f * (im[i * D + j] + im[j * D + i]));
}

// ACC = I + 2A + A^2   (= (I+A)^2)
__global__ void k_g0(float2* __restrict__ ACC, const float2* __restrict__ A,
                     const float2* __restrict__ A2) {
    int idx = blockIdx.x * 256 + threadIdx.x;
    float2 a = A[idx], p = A2[idx];
    float dgl = ((idx >> 10) == (idx & (D - 1))) ? 1.f : 0.f;
    ACC[idx] = make_float2(dgl + 2.f * a.x + p.x, 2.f * a.y + p.y);
}

__global__ void k_scales(const float* __restrict__ ls) {
    int d = blockIdx.x * 256 + threadIdx.x;
    if (d >= D) return;
    g_s[d]    = make_float2(expf(ls[d]), 0.f);
    g_sinv[d] = make_float2(expf(-ls[d]), 0.f);
}

__global__ void k_ops(const float* __restrict__ ld_, const float* __restrict__ lf_,
                      const float* __restrict__ lawre, const float* __restrict__ lawim,
                      const float* __restrict__ dtp) {
    int d = blockIdx.x * 256 + threadIdx.x;
    if (d >= D) return;
    float dtv = dtp[0];
    float lre = -expf(ld_[d]) + lawre[d];
    float lim = lf_[d] + lawim[d];
    // Lam.re = -softplus(-lre)
    float z = -lre;
    float sp = (z > 0.f) ? (z + log1pf(expf(-z))) : log1pf(expf(z));
    float2 Z = make_float2(-sp * dtv, lim * dtv);
    float ex = expf(Z.x);
    float sy, cy;
    sincosf(Z.y, &sy, &cy);
    float2 ez = make_float2(ex * cy, ex * sy);
    g_opd[d] = ez;
    float az2 = Z.x * Z.x + Z.y * Z.y;
    float2 phi;
    if (sqrtf(az2) < 1e-4f) {
        float2 z2 = cmulf(Z, Z);
        phi = make_float2(1.f + 0.5f * Z.x + z2.x * (1.f / 6.f),
                          0.5f * Z.y + z2.y * (1.f / 6.f));
    } else {
        float2 num = make_float2(ez.x - 1.f, ez.y);
        float inv = 1.f / az2;
        phi = make_float2((num.x * Z.x + num.y * Z.y) * inv,
                          (num.y * Z.x - num.x * Z.y) * inv);
    }
    g_opf[d] = make_float2(phi.x * dtv, phi.y * dtv);
}

// out[b,o] = bias[o] + sum_k cat(lo,hi)[b,k] * w[o,k] ; one block per o, 128 thr
__global__ void k_smallgemm(const float* __restrict__ lo, const float* __restrict__ hi,
                            const float* __restrict__ w, const float* __restrict__ bias,
                            float* __restrict__ outp) {
    int o = blockIdx.x;
    int tid = threadIdx.x;
    float part[BATCH];
#pragma unroll
    for (int b = 0; b < BATCH; ++b) part[b] = 0.f;
    const float* wr = w + (size_t)o * (2 * D);
    for (int k = tid; k < 2 * D; k += 128) {
        float wv = wr[k];
        const float* src = (k < D) ? (lo + k) : (hi + (k - D));
#pragma unroll
        for (int b = 0; b < BATCH; ++b) part[b] = fmaf(src[b * D], wv, part[b]);
    }
    __shared__ float red[BATCH][128];
#pragma unroll
    for (int b = 0; b < BATCH; ++b) red[b][tid] = part[b];
    __syncthreads();
    if (tid < BATCH) {
        float s = bias[o];
#pragma unroll 8
        for (int j = 0; j < 128; ++j) s += red[tid][j];
        outp[tid * 2 * D + o] = s;
    }
}

// flux_next = flux * (sigmoid(dre) + i*dim) + (xr + i*xi); also writes output planes
__global__ void k_flux(const float* __restrict__ fre, const float* __restrict__ fim,
                       const float* __restrict__ dre, const float* __restrict__ dim_,
                       const float* __restrict__ xm, float* __restrict__ out) {
    int idx = blockIdx.x * 256 + threadIdx.x;  // BATCH*D
    int b = idx >> 10, d = idx & (D - 1);
    float2 dec = make_float2(1.f / (1.f + expf(-dre[d])), dim_[d]);
    float2 f = make_float2(fre[idx], fim[idx]);
    float2 fn = cmulf(f, dec);
    fn.x += xm[b * 2 * D + d];
    fn.y += xm[b * 2 * D + D + d];
    g_fre[idx] = fn.x;
    g_fim[idx] = fn.y;
    out[2 * TB * D + idx] = fn.x;
    out[2 * TB * D + BATCH * D + idx] = fn.y;
}

// S2[b,d] = opf[d] * source[b,d]
__global__ void k_source(const float* __restrict__ proj) {
    int idx = blockIdx.x * 256 + threadIdx.x;  // BATCH*D
    int b = idx >> 10, d = idx & (D - 1);
    float2 src = make_float2(proj[b * 2 * D + d], proj[b * 2 * D + D + d]);
    g_S2[idx] = cmulf(g_opf[d], src);
}

// t[b,i] = sum_j M[i,j] * S2[b,j] ; one block per i, 128 thr
__global__ void k_tsmall() {
    int i = blockIdx.x;
    int tid = threadIdx.x;
    float2 part[BATCH];
#pragma unroll
    for (int b = 0; b < BATCH; ++b) part[b] = make_float2(0.f, 0.f);
    for (int j = tid; j < D; j += 128) {
        float2 m = g_M[(size_t)i * D + j];
#pragma unroll
        for (int b = 0; b < BATCH; ++b) {
            float2 s = g_S2[b * D + j];
            part[b].x = fmaf(m.x, s.x, fmaf(-m.y, s.y, part[b].x));
            part[b].y = fmaf(m.x, s.y, fmaf(m.y, s.x, part[b].y));
        }
    }
    __shared__ float2 red[BATCH][128];
#pragma unroll
    for (int b = 0; b < BATCH; ++b) red[b][tid] = part[b];
    __syncthreads();
    if (tid < BATCH) {
        float2 s = make_float2(0.f, 0.f);
#pragma unroll 8
        for (int j = 0; j < 128; ++j) {
            s.x += red[tid][j].x;
            s.y += red[tid][j].y;
        }
        g_t[tid * D + i] = s;
    }
}

// pack [h|x] into complex HX (TB x 2D)
__global__ void k_pack(const float* __restrict__ hre, const float* __restrict__ him,
                       const float* __restrict__ xre, const float* __restrict__ xim) {
    int idx = blockIdx.x * 256 + threadIdx.x;  // TB*2D
    int n = idx >> 11, k = idx & (2 * D - 1);
    float2 v;
    if (k < D)
        v = make_float2(hre[n * D + k], him[n * D + k]);
    else
        v = make_float2(xre[n * D + k - D], xim[n * D + k - D]);
    g_HX[idx] = v;
}

// out planes: re/im of C + t[batch]
__global__ void k_epi(float* __restrict__ out) {
    int idx = blockIdx.x * 256 + threadIdx.x;  // TB*D
    int n = idx >> 10, i = idx & (D - 1);
    int b = n >> 8;  // spatial = 256
    float2 v = g_C[idx];
    float2 tv = g_t[b * D + i];
    out[idx] = v.x + tv.x;
    out[TB * D + idx] = v.y + tv.y;
}

// ---------------- complex GEMM ----------------
// C[m,n] = sum_k Aop[m,k] * Bop[k,n] (+ Aepi[m,n] if ADDA)
// Aop[m,k] = A[m,k] * (SCALEA ? ascale[k] : 1)
// Bop[k,n] = TRANSB ? (CONJB ? conj(B[n,k]) : B[n,k]) : B[k,n]
// Tile 128x64xK16, 256 threads, 8x4 complex per thread, double-buffered smem.
template <bool TRANSB, bool CONJB, bool ADDA, bool SCALEA>
__global__ void __launch_bounds__(256, 1)
cgemm_k(const float2* __restrict__ A, int lda, const float2* __restrict__ B, int ldb,
        float2* __restrict__ C, int ldc, int K, const float2* __restrict__ ascale,
        const float2* __restrict__ Aepi) {
    __shared__ float2 As[2][16][128];
    __shared__ float2 Bs[2][16][64];

    const int tid = threadIdx.x;
    const int m0 = blockIdx.x * 128;
    const int n0 = blockIdx.y * 64;
    const int ty = tid >> 4;   // 0..15 row group
    const int txx = tid & 15;  // 0..15 col group

    float2 aS[4][2];  // staged A frags (already scaled)
    float2 bS[2][2];  // staged B frags (already conj'd)

    auto loadA = [&](int kt) {
#pragma unroll
        for (int i = 0; i < 4; ++i) {
            int idx = tid + 256 * i;
            int row = idx >> 3;
            int kk = (idx & 7) << 1;
            float4 v = *reinterpret_cast<const float4*>(
                A + (size_t)(m0 + row) * lda + kt + kk);
            float2 a0 = make_float2(v.x, v.y);
            float2 a1 = make_float2(v.z, v.w);
            if (SCALEA) {
                a0 = cmulf(a0, ascale[kt + kk]);
                a1 = cmulf(a1, ascale[kt + kk + 1]);
            }
            aS[i][0] = a0;
            aS[i][1] = a1;
        }
    };
    auto storeA = [&](int buf) {
#pragma unroll
        for (int i = 0; i < 4; ++i) {
            int idx = tid + 256 * i;
            int row = idx >> 3;
            int kk = (idx & 7) << 1;
            As[buf][kk][row] = aS[i][0];
            As[buf][kk + 1][row] = aS[i][1];
        }
    };
    auto loadB = [&](int kt) {
        if (TRANSB) {
#pragma unroll
            for (int i = 0; i < 2; ++i) {
                int idx = tid + 256 * i;
                int col = idx >> 3;
                int kk = (idx & 7) << 1;
                float4 v = *reinterpret_cast<const float4*>(
                    B + (size_t)(n0 + col) * ldb + kt + kk);
                float2 b0 = make_float2(v.x, CONJB ? -v.y : v.y);
                float2 b1 = make_float2(v.z, CONJB ? -v.w : v.w);
                bS[i][0] = b0;
                bS[i][1] = b1;
            }
        } else {
#pragma unroll
            for (int i = 0; i < 2; ++i) {
                int idx = tid + 256 * i;
                int kk = idx >> 5;
                int colq = (idx & 31) << 1;
                float4 v = *reinterpret_cast<const float4*>(
                    B + (size_t)(kt + kk) * ldb + n0 + colq);
                bS[i][0] = make_float2(v.x, v.y);
                bS[i][1] = make_float2(v.z, v.w);
            }
        }
    };
    auto storeB = [&](int buf) {
        if (TRANSB) {
#pragma unroll
            for (int i = 0; i < 2; ++i) {
                int idx = tid + 256 * i;
                int col = idx >> 3;
                int kk = (idx & 7) << 1;
                Bs[buf][kk][col] = bS[i][0];
                Bs[buf][kk + 1][col] = bS[i][1];
            }
        } else {
#pragma unroll
            for (int i = 0; i < 2; ++i) {
                int idx = tid + 256 * i;
                int kk = idx >> 5;
                int colq = (idx & 31) << 1;
                Bs[buf][kk][colq] = bS[i][0];
                Bs[buf][kk][colq + 1] = bS[i][1];
            }
        }
    };

    float2 acc[8][4];
#pragma unroll
    for (int r = 0; r < 8; ++r)
#pragma unroll
        for (int c = 0; c < 4; ++c) acc[r][c] = make_float2(0.f, 0.f);

    const int ntiles = K >> 4;
    loadA(0);
    loadB(0);
    storeA(0);
    storeB(0);
    __syncthreads();

    for (int t = 0; t < ntiles; ++t) {
        int cur = t & 1;
        if (t + 1 < ntiles) {
            loadA((t + 1) << 4);
            loadB((t + 1) << 4);
        }
#pragma unroll
        for (int k = 0; k < 16; ++k) {
            float2 a[8], b[4];
#pragma unroll
            for (int r = 0; r < 8; r += 2) {
                float4 v = *reinterpret_cast<const float4*>(&As[cur][k][ty * 8 + r]);
                a[r] = make_float2(v.x, v.y);
                a[r + 1] = make_float2(v.z, v.w);
            }
#pragma unroll
            for (int c = 0; c < 4; ++c) b[c] = Bs[cur][k][txx + 16 * c];
#pragma unroll
            for (int r = 0; r < 8; ++r)
#pragma unroll
                for (int c = 0; c < 4; ++c) {
                    acc[r][c].x = fmaf(a[r].x, b[c].x, acc[r][c].x);
                    acc[r][c].x = fmaf(-a[r].y, b[c].y, acc[r][c].x);
                    acc[r][c].y = fmaf(a[r].x, b[c].y, acc[r][c].y);
                    acc[r][c].y = fmaf(a[r].y, b[c].x, acc[r][c].y);
                }
        }
        if (t + 1 < ntiles) {
            storeA(cur ^ 1);
            storeB(cur ^ 1);
        }
        __syncthreads();
    }

#pragma unroll
    for (int r = 0; r < 8; ++r) {
        int gi = m0 + ty * 8 + r;
#pragma unroll
        for (int c = 0; c < 4; ++c) {
            int gj = n0 + txx + 16 * c;
            float2 v = acc[r][c];
            if (ADDA) {
                float2 e = Aepi[(size_t)gi * ldc + gj];
                v.x += e.x;
                v.y += e.y;
            }
            C[(size_t)gi * ldc + gj] = v;
        }
    }
}

// ---------------- host orchestration ----------------
static float2* symf2(const void* s) {
    void* p = nullptr;
    cudaGetSymbolAddress(&p, s);
    return (float2*)p;
}
static float* symf(const void* s) {
    void* p = nullptr;
    cudaGetSymbolAddress(&p, s);
    return (float*)p;
}

static void cayley(const float* re, const float* im, float2* SA, float2* SP, float2* SP2,
                   float2* ACCa, float2* ACCb, float2* OUT) {
    k_buildA<<<D * D / 256, 256>>>(SA, re, im);
    dim3 g(D / 128, D / 64);
    // P = A^2
    cgemm_k<false, false, false, false><<<g, 256>>>(SA, D, SA, D, SP, D, D, nullptr, nullptr);
    // ACC = (I+A)^2
    k_g0<<<D * D / 256, 256>>>(ACCa, SA, SP);
    float2* acc = ACCa;
    float2* accN = ACCb;
    float2* p = SP;
    float2* pN = SP2;
    for (int i = 0; i < 5; ++i) {
        float2* dst = (i == 4) ? OUT : accN;
        // dst = ACC*P + ACC   (== ACC*(I+P))
        cgemm_k<false, false, true, false><<<g, 256>>>(acc, D, p, D, dst, D, D, nullptr, acc);
        if (i < 4) {
            cgemm_k<false, false, false, false><<<g, 256>>>(p, D, p, D, pN, D, D, nullptr, nullptr);
            float2* tp = p; p = pN; pN = tp;
        }
        accN = acc;
        acc = dst;
    }
}

extern "C" void kernel_launch(void* const* d_in, const int* in_sizes, int n_in,
                              void* d_out, int out_size) {
    const float* h_re   = (const float*)d_in[0];
    const float* h_im   = (const float*)d_in[1];
    const float* x_re   = (const float*)d_in[2];
    const float* x_im   = (const float*)d_in[3];
    const float* xg_re  = (const float*)d_in[4];
    const float* xg_im  = (const float*)d_in[5];
    const float* fl_re  = (const float*)d_in[6];
    const float* fl_im  = (const float*)d_in[7];
    const float* dt     = (const float*)d_in[8];
    const float* u_re   = (const float*)d_in[9];
    const float* u_im   = (const float*)d_in[10];
    const float* v_re   = (const float*)d_in[11];
    const float* v_im   = (const float*)d_in[12];
    const float* lsig   = (const float*)d_in[13];
    const float* dec_re = (const float*)d_in[14];
    const float* dec_im = (const float*)d_in[15];
    const float* mix_w  = (const float*)d_in[16];
    const float* mix_b  = (const float*)d_in[17];
    const float* proj_w = (const float*)d_in[18];
    const float* proj_b = (const float*)d_in[19];
    const float* ld_    = (const float*)d_in[20];
    const float* lf_    = (const float*)d_in[21];
    const float* law_re = (const float*)d_in[22];
    const float* law_im = (const float*)d_in[23];
    float* out = (float*)d_out;

    float2* SA   = symf2(g_SA);
    float2* SP   = symf2(g_SP);
    float2* SP2  = symf2(g_SP2);
    float2* ACCa = symf2(g_ACCa);
    float2* ACCb = symf2(g_ACCb);
    float2* U    = symf2(g_U);
    float2* V    = symf2(g_V);
    float2* Mm   = symf2(g_M);
    float2* Minv = symf2(g_Minv);
    float2* W    = symf2(g_W);
    float2* HX   = symf2(g_HX);
    float2* Cc   = symf2(g_C);
    float2* sd   = symf2(g_s);
    float2* sinv = symf2(g_sinv);
    float2* opd  = symf2(g_opd);
    float2* opf  = symf2(g_opf);
    float*  xm   = symf(g_xm);
    float*  fre  = symf(g_fre);
    float*  fim  = symf(g_fim);
    float*  proj = symf(g_proj);

    // Cayley transforms
    cayley(u_re, u_im, SA, SP, SP2, ACCa, ACCb, U);
    cayley(v_re, v_im, SA, SP, SP2, ACCa, ACCb, V);

    // scales + transition operators
    k_scales<<<4, 256>>>(lsig);
    k_ops<<<4, 256>>>(ld_, lf_, law_re, law_im, dt);

    dim3 gdd(D / 128, D / 64);
    // M = (U * s) V^H     [A=U scaled by s along k, B=V trans+conj]
    cgemm_k<true, true, false, true><<<gdd, 256>>>(U, D, V, D, Mm, D, D, sd, nullptr);
    // M_inv = (V * s^-1) U^H
    cgemm_k<true, true, false, true><<<gdd, 256>>>(V, D, U, D, Minv, D, D, sinv, nullptr);
    // W1 = (M * op_decay_cols) @ M_inv ; W2 = (M * op_forcing_cols) @ M_inv
    cgemm_k<false, false, false, true><<<gdd, 256>>>(Mm, D, Minv, D, W, 2 * D, D, opd, nullptr);
    cgemm_k<false, false, false, true><<<gdd, 256>>>(Mm, D, Minv, D, W + D, 2 * D, D, opf, nullptr);

    // flux tracker chain
    k_smallgemm<<<2 * D, 128>>>(xg_re, xg_im, mix_w, mix_b, xm);
    k_flux<<<BATCH * D / 256, 256>>>(fl_re, fl_im, dec_re, dec_im, xm, out);
    k_smallgemm<<<2 * D, 128>>>(fre, fim, proj_w, proj_b, proj);
    k_source<<<BATCH * D / 256, 256>>>(proj);
    k_tsmall<<<D, 128>>>();

    // main pass: C = [h|x] @ [W1|W2]^T
    k_pack<<<TB * 2 * D / 256, 256>>>(h_re, h_im, x_re, x_im);
    dim3 gmain(TB / 128, D / 64);
    cgemm_k<true, false, false, false><<<gmain, 256>>>(HX, 2 * D, W, 2 * D, Cc, D, 2 * D,
                                                       nullptr, nullptr);
    k_epi<<<TB * D / 256, 256>>>(out);

    (void)in_sizes; (void)n_in; (void)out_size;
}

// round 4
// speedup vs baseline: 1.1767x; 1.1767x over previous
#include <cuda_runtime.h>
#include <math.h>

#define D 1024
#define TB 4096
#define BATCH 16
// spatial = TB/BATCH = 256

typedef unsigned long long ull;

// ---------------- device scratch (static globals; no allocation) ----------------
__device__ float2 g_SA  [D*D];
__device__ float2 g_SP  [D*D];
__device__ float2 g_SP2 [D*D];
__device__ float2 g_ACCa[D*D];
__device__ float2 g_ACCb[D*D];
__device__ float2 g_U   [D*D];
__device__ float2 g_V   [D*D];
__device__ float2 g_M   [D*D];
__device__ float2 g_Minv[D*D];
__device__ float2 g_W   [D*2*D];    // row i: [0:D)=W1[i,:], [D:2D)=W2[i,:]
__device__ float2 g_HX  [TB*2*D];   // packed [h|x] complex
__device__ float2 g_C   [TB*D];
__device__ float2 g_s   [D];
__device__ float2 g_sinv[D];
__device__ float2 g_opd [D];
__device__ float2 g_opf [D];
__device__ float  g_xm  [BATCH*2*D];
__device__ float  g_fre [BATCH*D];
__device__ float  g_fim [BATCH*D];
__device__ float  g_proj[BATCH*2*D];
__device__ float2 g_S2  [BATCH*D];
__device__ float2 g_t   [BATCH*D];

__device__ __forceinline__ float2 cmulf(float2 a, float2 b) {
    return make_float2(fmaf(a.x, b.x, -a.y * b.y), fmaf(a.x, b.y, a.y * b.x));
}

// ---------------- packed f32x2 helpers ----------------
__device__ __forceinline__ ull ffma2(ull a, ull b, ull c) {
    ull d;
    asm("fma.rn.f32x2 %0, %1, %2, %3;" : "=l"(d) : "l"(a), "l"(b), "l"(c));
    return d;
}
__device__ __forceinline__ ull fmul2(ull a, ull b) {
    ull d;
    asm("mul.rn.f32x2 %0, %1, %2;" : "=l"(d) : "l"(a), "l"(b));
    return d;
}
__device__ __forceinline__ ull dup2(float x) {
    ull d;
    asm("mov.b64 %0, {%1, %1};" : "=l"(d) : "f"(x));
    return d;
}
__device__ __forceinline__ void unpack2(ull v, float& lo, float& hi) {
    asm("mov.b64 {%0, %1}, %2;" : "=f"(lo), "=f"(hi) : "l"(v));
}
__device__ __forceinline__ ull d2l(double v) { return __double_as_longlong(v); }

// ---------------- elementwise / small kernels ----------------

// A = 0.5(re - re^T) + i*0.5(im + im^T)
__global__ void k_buildA(float2* __restrict__ A, const float* __restrict__ re,
                         const float* __restrict__ im) {
    int idx = blockIdx.x * 256 + threadIdx.x;
    int i = idx >> 10, j = idx & (D - 1);
    A[idx] = make_float2(0.5f * (re[i * D + j] - re[j * D + i]),
                         0.5f * (im[i * D + j] + im[j * D + i]));
}

// ACC = I + 2A + A^2   (= (I+A)^2)
__global__ void k_g0(float2* __restrict__ ACC, const float2* __restrict__ A,
                     const float2* __restrict__ A2) {
    int idx = blockIdx.x * 256 + threadIdx.x;
    float2 a = A[idx], p = A2[idx];
    float dgl = ((idx >> 10) == (idx & (D - 1))) ? 1.f : 0.f;
    ACC[idx] = make_float2(dgl + 2.f * a.x + p.x, 2.f * a.y + p.y);
}

__global__ void k_scales(const float* __restrict__ ls) {
    int d = blockIdx.x * 256 + threadIdx.x;
    if (d >= D) return;
    g_s[d]    = make_float2(expf(ls[d]), 0.f);
    g_sinv[d] = make_float2(expf(-ls[d]), 0.f);
}

__global__ void k_ops(const float* __restrict__ ld_, const float* __restrict__ lf_,
                      const float* __restrict__ lawre, const float* __restrict__ lawim,
                      const float* __restrict__ dtp) {
    int d = blockIdx.x * 256 + threadIdx.x;
    if (d >= D) return;
    float dtv = dtp[0];
    float lre = -expf(ld_[d]) + lawre[d];
    float lim = lf_[d] + lawim[d];
    // Lam.re = -softplus(-lre)
    float z = -lre;
    float sp = (z > 0.f) ? (z + log1pf(expf(-z))) : log1pf(expf(z));
    float2 Z = make_float2(-sp * dtv, lim * dtv);
    float ex = expf(Z.x);
    float sy, cy;
    sincosf(Z.y, &sy, &cy);
    float2 ez = make_float2(ex * cy, ex * sy);
    g_opd[d] = ez;
    float az2 = Z.x * Z.x + Z.y * Z.y;
    float2 phi;
    if (sqrtf(az2) < 1e-4f) {
        float2 z2 = cmulf(Z, Z);
        phi = make_float2(1.f + 0.5f * Z.x + z2.x * (1.f / 6.f),
                          0.5f * Z.y + z2.y * (1.f / 6.f));
    } else {
        float2 num = make_float2(ez.x - 1.f, ez.y);
        float inv = 1.f / az2;
        phi = make_float2((num.x * Z.x + num.y * Z.y) * inv,
                          (num.y * Z.x - num.x * Z.y) * inv);
    }
    g_opf[d] = make_float2(phi.x * dtv, phi.y * dtv);
}

// out[b,o] = bias[o] + sum_k cat(lo,hi)[b,k] * w[o,k] ; one block per o, 128 thr
__global__ void k_smallgemm(const float* __restrict__ lo, const float* __restrict__ hi,
                            const float* __restrict__ w, const float* __restrict__ bias,
                            float* __restrict__ outp) {
    int o = blockIdx.x;
    int tid = threadIdx.x;
    float part[BATCH];
#pragma unroll
    for (int b = 0; b < BATCH; ++b) part[b] = 0.f;
    const float* wr = w + (size_t)o * (2 * D);
    for (int k = tid; k < 2 * D; k += 128) {
        float wv = wr[k];
        const float* src = (k < D) ? (lo + k) : (hi + (k - D));
#pragma unroll
        for (int b = 0; b < BATCH; ++b) part[b] = fmaf(src[b * D], wv, part[b]);
    }
    __shared__ float red[BATCH][128];
#pragma unroll
    for (int b = 0; b < BATCH; ++b) red[b][tid] = part[b];
    __syncthreads();
    if (tid < BATCH) {
        float s = bias[o];
#pragma unroll 8
        for (int j = 0; j < 128; ++j) s += red[tid][j];
        outp[tid * 2 * D + o] = s;
    }
}

// flux_next = flux * (sigmoid(dre) + i*dim) + (xr + i*xi); also writes output planes
__global__ void k_flux(const float* __restrict__ fre, const float* __restrict__ fim,
                       const float* __restrict__ dre, const float* __restrict__ dim_,
                       const float* __restrict__ xm, float* __restrict__ out) {
    int idx = blockIdx.x * 256 + threadIdx.x;  // BATCH*D
    int b = idx >> 10, d = idx & (D - 1);
    float2 dec = make_float2(1.f / (1.f + expf(-dre[d])), dim_[d]);
    float2 f = make_float2(fre[idx], fim[idx]);
    float2 fn = cmulf(f, dec);
    fn.x += xm[b * 2 * D + d];
    fn.y += xm[b * 2 * D + D + d];
    g_fre[idx] = fn.x;
    g_fim[idx] = fn.y;
    out[2 * TB * D + idx] = fn.x;
    out[2 * TB * D + BATCH * D + idx] = fn.y;
}

// S2[b,d] = opf[d] * source[b,d]
__global__ void k_source(const float* __restrict__ proj) {
    int idx = blockIdx.x * 256 + threadIdx.x;  // BATCH*D
    int b = idx >> 10, d = idx & (D - 1);
    float2 src = make_float2(proj[b * 2 * D + d], proj[b * 2 * D + D + d]);
    g_S2[idx] = cmulf(g_opf[d], src);
}

// t[b,i] = sum_j M[i,j] * S2[b,j] ; one block per i, 128 thr
__global__ void k_tsmall() {
    int i = blockIdx.x;
    int tid = threadIdx.x;
    float2 part[BATCH];
#pragma unroll
    for (int b = 0; b < BATCH; ++b) part[b] = make_float2(0.f, 0.f);
    for (int j = tid; j < D; j += 128) {
        float2 m = g_M[(size_t)i * D + j];
#pragma unroll
        for (int b = 0; b < BATCH; ++b) {
            float2 s = g_S2[b * D + j];
            part[b].x = fmaf(m.x, s.x, fmaf(-m.y, s.y, part[b].x));
            part[b].y = fmaf(m.x, s.y, fmaf(m.y, s.x, part[b].y));
        }
    }
    __shared__ float2 red[BATCH][128];
#pragma unroll
    for (int b = 0; b < BATCH; ++b) red[b][tid] = part[b];
    __syncthreads();
    if (tid < BATCH) {
        float2 s = make_float2(0.f, 0.f);
#pragma unroll 8
        for (int j = 0; j < 128; ++j) {
            s.x += red[tid][j].x;
            s.y += red[tid][j].y;
        }
        g_t[tid * D + i] = s;
    }
}

// pack [h|x] into complex HX (TB x 2D)
__global__ void k_pack(const float* __restrict__ hre, const float* __restrict__ him,
                       const float* __restrict__ xre, const float* __restrict__ xim) {
    int idx = blockIdx.x * 256 + threadIdx.x;  // TB*2D
    int n = idx >> 11, k = idx & (2 * D - 1);
    float2 v;
    if (k < D)
        v = make_float2(hre[n * D + k], him[n * D + k]);
    else
        v = make_float2(xre[n * D + k - D], xim[n * D + k - D]);
    g_HX[idx] = v;
}

// out planes: re/im of C + t[batch]
__global__ void k_epi(float* __restrict__ out) {
    int idx = blockIdx.x * 256 + threadIdx.x;  // TB*D
    int n = idx >> 10, i = idx & (D - 1);
    int b = n >> 8;  // spatial = 256
    float2 v = g_C[idx];
    float2 tv = g_t[b * D + i];
    out[idx] = v.x + tv.x;
    out[TB * D + idx] = v.y + tv.y;
}

// ---------------- complex GEMM (FFMA2 / f32x2 inner loop) ----------------
// C[m,n] = sum_k Aop[m,k] * Bop[k,n] (+ Aepi[m,n] if ADDA)
// Aop[m,k] = A[m,k] * (SCALEA ? ascale[k] : 1)
// Bop[k,n] = TRANSB ? (CONJB ? conj(B[n,k]) : B[n,k]) : B[k,n]
// Tile 128x64xK8, 256 threads, 8x4 complex per thread (row-pair packed),
// A stored in smem as de-interleaved re/im planes for packed double2 loads.
#define AW 132  // padded plane width (floats): conflict-free staging stores

template <bool TRANSB, bool CONJB, bool ADDA, bool SCALEA>
__global__ void __launch_bounds__(256, 1)
cgemm_k(const float2* __restrict__ A, int lda, const float2* __restrict__ B, int ldb,
        float2* __restrict__ C, int ldc, int K, const float2* __restrict__ ascale,
        const float2* __restrict__ Aepi) {
    __shared__ __align__(16) float AsRe[2][8][AW];
    __shared__ __align__(16) float AsIm[2][8][AW];
    __shared__ __align__(16) float2 Bs[2][8][64];

    const int tid = threadIdx.x;
    const int m0 = blockIdx.x * 128;
    const int n0 = blockIdx.y * 64;
    const int ty = tid >> 4;   // 0..15: rows ty*8 .. ty*8+7
    const int txx = tid & 15;  // cols txx + 16*c

    float2 aS[2][2];  // staged A (scaled)
    float2 bS[2];     // staged B (conj applied)

    auto loadA = [&](int kt) {
#pragma unroll
        for (int i = 0; i < 2; ++i) {
            int idx = tid + 256 * i;
            int row = idx >> 2;
            int kk = (idx & 3) << 1;
            float4 v = *reinterpret_cast<const float4*>(
                A + (size_t)(m0 + row) * lda + kt + kk);
            float2 a0 = make_float2(v.x, v.y);
            float2 a1 = make_float2(v.z, v.w);
            if (SCALEA) {
                a0 = cmulf(a0, ascale[kt + kk]);
                a1 = cmulf(a1, ascale[kt + kk + 1]);
            }
            aS[i][0] = a0;
            aS[i][1] = a1;
        }
    };
    auto storeA = [&](int buf) {
#pragma unroll
        for (int i = 0; i < 2; ++i) {
            int idx = tid + 256 * i;
            int row = idx >> 2;
            int kk = (idx & 3) << 1;
            AsRe[buf][kk][row]     = aS[i][0].x;
            AsIm[buf][kk][row]     = aS[i][0].y;
            AsRe[buf][kk + 1][row] = aS[i][1].x;
            AsIm[buf][kk + 1][row] = aS[i][1].y;
        }
    };
    auto loadB = [&](int kt) {
        if (TRANSB) {
            int col = tid >> 2;
            int kk = (tid & 3) << 1;
            float4 v = *reinterpret_cast<const float4*>(
                B + (size_t)(n0 + col) * ldb + kt + kk);
            bS[0] = make_float2(v.x, CONJB ? -v.y : v.y);
            bS[1] = make_float2(v.z, CONJB ? -v.w : v.w);
        } else {
            int kk = tid >> 5;
            int col = (tid & 31) << 1;
            float4 v = *reinterpret_cast<const float4*>(
                B + (size_t)(kt + kk) * ldb + n0 + col);
            bS[0] = make_float2(v.x, v.y);
            bS[1] = make_float2(v.z, v.w);
        }
    };
    auto storeB = [&](int buf) {
        if (TRANSB) {
            int col = tid >> 2;
            int kk = (tid & 3) << 1;
            Bs[buf][kk][col] = bS[0];
            Bs[buf][kk + 1][col] = bS[1];
        } else {
            int kk = tid >> 5;
            int col = (tid & 31) << 1;
            Bs[buf][kk][col] = bS[0];
            Bs[buf][kk][col + 1] = bS[1];
        }
    };

    ull accR[4][4], accI[4][4];
    const ull ZERO = dup2(0.f);
#pragma unroll
    for (int p = 0; p < 4; ++p)
#pragma unroll
        for (int c = 0; c < 4; ++c) { accR[p][c] = ZERO; accI[p][c] = ZERO; }

    const ull NEG1 = dup2(-1.f);
    const int ntiles = K >> 3;
    loadA(0);
    loadB(0);
    storeA(0);
    storeB(0);
    __syncthreads();

    for (int t = 0; t < ntiles; ++t) {
        int cur = t & 1;
        if (t + 1 < ntiles) {
            loadA((t + 1) << 3);
            loadB((t + 1) << 3);
        }
#pragma unroll
        for (int k = 0; k < 8; ++k) {
            double2 r01 = *reinterpret_cast<const double2*>(&AsRe[cur][k][ty * 8]);
            double2 r23 = *reinterpret_cast<const double2*>(&AsRe[cur][k][ty * 8 + 4]);
            double2 i01 = *reinterpret_cast<const double2*>(&AsIm[cur][k][ty * 8]);
            double2 i23 = *reinterpret_cast<const double2*>(&AsIm[cur][k][ty * 8 + 4]);
            ull ar[4] = {d2l(r01.x), d2l(r01.y), d2l(r23.x), d2l(r23.y)};
            ull ai[4] = {d2l(i01.x), d2l(i01.y), d2l(i23.x), d2l(i23.y)};
            ull nai[4];
#pragma unroll
            for (int p = 0; p < 4; ++p) nai[p] = fmul2(ai[p], NEG1);
#pragma unroll
            for (int c = 0; c < 4; ++c) {
                float2 b = Bs[cur][k][txx + 16 * c];
                ull br2 = dup2(b.x);
                ull bi2 = dup2(b.y);
#pragma unroll
                for (int p = 0; p < 4; ++p) {
                    accR[p][c] = ffma2(ar[p], br2, accR[p][c]);
                    accR[p][c] = ffma2(nai[p], bi2, accR[p][c]);
                    accI[p][c] = ffma2(ar[p], bi2, accI[p][c]);
                    accI[p][c] = ffma2(ai[p], br2, accI[p][c]);
                }
            }
        }
        if (t + 1 < ntiles) {
            storeA(cur ^ 1);
            storeB(cur ^ 1);
        }
        __syncthreads();
    }

#pragma unroll
    for (int p = 0; p < 4; ++p) {
        int gi = m0 + ty * 8 + 2 * p;
#pragma unroll
        for (int c = 0; c < 4; ++c) {
            int gj = n0 + txx + 16 * c;
            float re0, re1, im0, im1;
            unpack2(accR[p][c], re0, re1);
            unpack2(accI[p][c], im0, im1);
            float2 v0 = make_float2(re0, im0);
            float2 v1 = make_float2(re1, im1);
            if (ADDA) {
                float2 e0 = Aepi[(size_t)gi * ldc + gj];
                float2 e1 = Aepi[(size_t)(gi + 1) * ldc + gj];
                v0.x += e0.x; v0.y += e0.y;
                v1.x += e1.x; v1.y += e1.y;
            }
            C[(size_t)gi * ldc + gj] = v0;
            C[(size_t)(gi + 1) * ldc + gj] = v1;
        }
    }
}

// ---------------- host orchestration ----------------
static float2* symf2(const void* s) {
    void* p = nullptr;
    cudaGetSymbolAddress(&p, s);
    return (float2*)p;
}
static float* symf(const void* s) {
    void* p = nullptr;
    cudaGetSymbolAddress(&p, s);
    return (float*)p;
}

static void cayley(const float* re, const float* im, float2* SA, float2* SP, float2* SP2,
                   float2* ACCa, float2* ACCb, float2* OUT) {
    k_buildA<<<D * D / 256, 256>>>(SA, re, im);
    dim3 g(D / 128, D / 64);
    // P = A^2
    cgemm_k<false, false, false, false><<<g, 256>>>(SA, D, SA, D, SP, D, D, nullptr, nullptr);
    // ACC = (I+A)^2
    k_g0<<<D * D / 256, 256>>>(ACCa, SA, SP);
    float2* acc = ACCa;
    float2* accN = ACCb;
    float2* p = SP;
    float2* pN = SP2;
    for (int i = 0; i < 5; ++i) {
        float2* dst = (i == 4) ? OUT : accN;
        // dst = ACC*P + ACC   (== ACC*(I+P))
        cgemm_k<false, false, true, false><<<g, 256>>>(acc, D, p, D, dst, D, D, nullptr, acc);
        if (i < 4) {
            cgemm_k<false, false, false, false><<<g, 256>>>(p, D, p, D, pN, D, D, nullptr, nullptr);
            float2* tp = p; p = pN; pN = tp;
        }
        accN = acc;
        acc = dst;
    }
}

extern "C" void kernel_launch(void* const* d_in, const int* in_sizes, int n_in,
                              void* d_out, int out_size) {
    const float* h_re   = (const float*)d_in[0];
    const float* h_im   = (const float*)d_in[1];
    const float* x_re   = (const float*)d_in[2];
    const float* x_im   = (const float*)d_in[3];
    const float* xg_re  = (const float*)d_in[4];
    const float* xg_im  = (const float*)d_in[5];
    const float* fl_re  = (const float*)d_in[6];
    const float* fl_im  = (const float*)d_in[7];
    const float* dt     = (const float*)d_in[8];
    const float* u_re   = (const float*)d_in[9];
    const float* u_im   = (const float*)d_in[10];
    const float* v_re   = (const float*)d_in[11];
    const float* v_im   = (const float*)d_in[12];
    const float* lsig   = (const float*)d_in[13];
    const float* dec_re = (const float*)d_in[14];
    const float* dec_im = (const float*)d_in[15];
    const float* mix_w  = (const float*)d_in[16];
    const float* mix_b  = (const float*)d_in[17];
    const float* proj_w = (const float*)d_in[18];
    const float* proj_b = (const float*)d_in[19];
    const float* ld_    = (const float*)d_in[20];
    const float* lf_    = (const float*)d_in[21];
    const float* law_re = (const float*)d_in[22];
    const float* law_im = (const float*)d_in[23];
    float* out = (float*)d_out;

    float2* SA   = symf2(g_SA);
    float2* SP   = symf2(g_SP);
    float2* SP2  = symf2(g_SP2);
    float2* ACCa = symf2(g_ACCa);
    float2* ACCb = symf2(g_ACCb);
    float2* U    = symf2(g_U);
    float2* V    = symf2(g_V);
    float2* Mm   = symf2(g_M);
    float2* Minv = symf2(g_Minv);
    float2* W    = symf2(g_W);
    float2* HX   = symf2(g_HX);
    float2* Cc   = symf2(g_C);
    float2* sd   = symf2(g_s);
    float2* sinv = symf2(g_sinv);
    float2* opd  = symf2(g_opd);
    float2* opf  = symf2(g_opf);
    float*  xm   = symf(g_xm);
    float*  fre  = symf(g_fre);
    float*  fim  = symf(g_fim);
    float*  proj = symf(g_proj);

    // Cayley transforms
    cayley(u_re, u_im, SA, SP, SP2, ACCa, ACCb, U);
    cayley(v_re, v_im, SA, SP, SP2, ACCa, ACCb, V);

    // scales + transition operators
    k_scales<<<4, 256>>>(lsig);
    k_ops<<<4, 256>>>(ld_, lf_, law_re, law_im, dt);

    dim3 gdd(D / 128, D / 64);
    // M = (U * s) V^H     [A=U scaled by s along k, B=V trans+conj]
    cgemm_k<true, true, false, true><<<gdd, 256>>>(U, D, V, D, Mm, D, D, sd, nullptr);
    // M_inv = (V * s^-1) U^H
    cgemm_k<true, true, false, true><<<gdd, 256>>>(V, D, U, D, Minv, D, D, sinv, nullptr);
    // W1 = (M * op_decay_cols) @ M_inv ; W2 = (M * op_forcing_cols) @ M_inv
    cgemm_k<false, false, false, true><<<gdd, 256>>>(Mm, D, Minv, D, W, 2 * D, D, opd, nullptr);
    cgemm_k<false, false, false, true><<<gdd, 256>>>(Mm, D, Minv, D, W + D, 2 * D, D, opf, nullptr);

    // flux tracker chain
    k_smallgemm<<<2 * D, 128>>>(xg_re, xg_im, mix_w, mix_b, xm);
    k_flux<<<BATCH * D / 256, 256>>>(fl_re, fl_im, dec_re, dec_im, xm, out);
    k_smallgemm<<<2 * D, 128>>>(fre, fim, proj_w, proj_b, proj);
    k_source<<<BATCH * D / 256, 256>>>(proj);
    k_tsmall<<<D, 128>>>();

    // main pass: C = [h|x] @ [W1|W2]^T
    k_pack<<<TB * 2 * D / 256, 256>>>(h_re, h_im, x_re, x_im);
    dim3 gmain(TB / 128, D / 64);
    cgemm_k<true, false, false, false><<<gmain, 256>>>(HX, 2 * D, W, 2 * D, Cc, D, 2 * D,
                                                       nullptr, nullptr);
    k_epi<<<TB * D / 256, 256>>>(out);

    (void)in_sizes; (void)n_in; (void)out_size;
}

// round 5
// speedup vs baseline: 1.1774x; 1.0006x over previous
#include <cuda_runtime.h>
#include <math.h>

#define D 1024
#define TB 4096
#define BATCH 16
// spatial = TB/BATCH = 256

typedef unsigned long long ull;

// ---------------- device scratch (static globals; no allocation) ----------------
__device__ float2 g_SA  [D*D];
__device__ float2 g_SP  [D*D];
__device__ float2 g_SP2 [D*D];
__device__ float2 g_ACCa[D*D];
__device__ float2 g_ACCb[D*D];
__device__ float2 g_U   [D*D];
__device__ float2 g_V   [D*D];
__device__ float2 g_M   [D*D];
__device__ float2 g_Minv[D*D];
__device__ float2 g_W   [D*2*D];    // row i: [0:D)=W1[i,:], [D:2D)=W2[i,:]
__device__ float2 g_HX  [TB*2*D];   // packed [h|x] complex
__device__ float2 g_C   [TB*D];
__device__ float2 g_s   [D];
__device__ float2 g_sinv[D];
__device__ float2 g_opd [D];
__device__ float2 g_opf [D];
__device__ float  g_xm  [BATCH*2*D];
__device__ float  g_fre [BATCH*D];
__device__ float  g_fim [BATCH*D];
__device__ float  g_proj[BATCH*2*D];
__device__ float2 g_S2  [BATCH*D];
__device__ float2 g_t   [BATCH*D];

__device__ __forceinline__ float2 cmulf(float2 a, float2 b) {
    return make_float2(fmaf(a.x, b.x, -a.y * b.y), fmaf(a.x, b.y, a.y * b.x));
}

// ---------------- packed f32x2 helpers ----------------
__device__ __forceinline__ ull ffma2(ull a, ull b, ull c) {
    ull d;
    asm("fma.rn.f32x2 %0, %1, %2, %3;" : "=l"(d) : "l"(a), "l"(b), "l"(c));
    return d;
}
__device__ __forceinline__ ull fmul2(ull a, ull b) {
    ull d;
    asm("mul.rn.f32x2 %0, %1, %2;" : "=l"(d) : "l"(a), "l"(b));
    return d;
}
__device__ __forceinline__ ull dup2(float x) {
    ull d;
    asm("mov.b64 %0, {%1, %1};" : "=l"(d) : "f"(x));
    return d;
}
__device__ __forceinline__ void unpack2(ull v, float& lo, float& hi) {
    asm("mov.b64 {%0, %1}, %2;" : "=f"(lo), "=f"(hi) : "l"(v));
}
__device__ __forceinline__ ull d2l(double v) { return __double_as_longlong(v); }

// ---------------- elementwise / small kernels ----------------

// A = 0.5(re - re^T) + i*0.5(im + im^T)
__global__ void k_buildA(float2* __restrict__ A, const float* __restrict__ re,
                         const float* __restrict__ im) {
    int idx = blockIdx.x * 256 + threadIdx.x;
    int i = idx >> 10, j = idx & (D - 1);
    A[idx] = make_float2(0.5f * (re[i * D + j] - re[j * D + i]),
                         0.5f * (im[i * D + j] + im[j * D + i]));
}

// ACC = I + 2A + A^2   (= (I+A)^2)
__global__ void k_g0(float2* __restrict__ ACC, const float2* __restrict__ A,
                     const float2* __restrict__ A2) {
    int idx = blockIdx.x * 256 + threadIdx.x;
    float2 a = A[idx], p = A2[idx];
    float dgl = ((idx >> 10) == (idx & (D - 1))) ? 1.f : 0.f;
    ACC[idx] = make_float2(dgl + 2.f * a.x + p.x, 2.f * a.y + p.y);
}

__global__ void k_scales(const float* __restrict__ ls) {
    int d = blockIdx.x * 256 + threadIdx.x;
    if (d >= D) return;
    g_s[d]    = make_float2(expf(ls[d]), 0.f);
    g_sinv[d] = make_float2(expf(-ls[d]), 0.f);
}

__global__ void k_ops(const float* __restrict__ ld_, const float* __restrict__ lf_,
                      const float* __restrict__ lawre, const float* __restrict__ lawim,
                      const float* __restrict__ dtp) {
    int d = blockIdx.x * 256 + threadIdx.x;
    if (d >= D) return;
    float dtv = dtp[0];
    float lre = -expf(ld_[d]) + lawre[d];
    float lim = lf_[d] + lawim[d];
    // Lam.re = -softplus(-lre)
    float z = -lre;
    float sp = (z > 0.f) ? (z + log1pf(expf(-z))) : log1pf(expf(z));
    float2 Z = make_float2(-sp * dtv, lim * dtv);
    float ex = expf(Z.x);
    float sy, cy;
    sincosf(Z.y, &sy, &cy);
    float2 ez = make_float2(ex * cy, ex * sy);
    g_opd[d] = ez;
    float az2 = Z.x * Z.x + Z.y * Z.y;
    float2 phi;
    if (sqrtf(az2) < 1e-4f) {
        float2 z2 = cmulf(Z, Z);
        phi = make_float2(1.f + 0.5f * Z.x + z2.x * (1.f / 6.f),
                          0.5f * Z.y + z2.y * (1.f / 6.f));
    } else {
        float2 num = make_float2(ez.x - 1.f, ez.y);
        float inv = 1.f / az2;
        phi = make_float2((num.x * Z.x + num.y * Z.y) * inv,
                          (num.y * Z.x - num.x * Z.y) * inv);
    }
    g_opf[d] = make_float2(phi.x * dtv, phi.y * dtv);
}

// out[b,o] = bias[o] + sum_k cat(lo,hi)[b,k] * w[o,k] ; one block per o, 128 thr
__global__ void k_smallgemm(const float* __restrict__ lo, const float* __restrict__ hi,
                            const float* __restrict__ w, const float* __restrict__ bias,
                            float* __restrict__ outp) {
    int o = blockIdx.x;
    int tid = threadIdx.x;
    float part[BATCH];
#pragma unroll
    for (int b = 0; b < BATCH; ++b) part[b] = 0.f;
    const float* wr = w + (size_t)o * (2 * D);
    for (int k = tid; k < 2 * D; k += 128) {
        float wv = wr[k];
        const float* src = (k < D) ? (lo + k) : (hi + (k - D));
#pragma unroll
        for (int b = 0; b < BATCH; ++b) part[b] = fmaf(src[b * D], wv, part[b]);
    }
    __shared__ float red[BATCH][128];
#pragma unroll
    for (int b = 0; b < BATCH; ++b) red[b][tid] = part[b];
    __syncthreads();
    if (tid < BATCH) {
        float s = bias[o];
#pragma unroll 8
        for (int j = 0; j < 128; ++j) s += red[tid][j];
        outp[tid * 2 * D + o] = s;
    }
}

// flux_next = flux * (sigmoid(dre) + i*dim) + (xr + i*xi); also writes output planes
__global__ void k_flux(const float* __restrict__ fre, const float* __restrict__ fim,
                       const float* __restrict__ dre, const float* __restrict__ dim_,
                       const float* __restrict__ xm, float* __restrict__ out) {
    int idx = blockIdx.x * 256 + threadIdx.x;  // BATCH*D
    int b = idx >> 10, d = idx & (D - 1);
    float2 dec = make_float2(1.f / (1.f + expf(-dre[d])), dim_[d]);
    float2 f = make_float2(fre[idx], fim[idx]);
    float2 fn = cmulf(f, dec);
    fn.x += xm[b * 2 * D + d];
    fn.y += xm[b * 2 * D + D + d];
    g_fre[idx] = fn.x;
    g_fim[idx] = fn.y;
    out[2 * TB * D + idx] = fn.x;
    out[2 * TB * D + BATCH * D + idx] = fn.y;
}

// S2[b,d] = opf[d] * source[b,d]
__global__ void k_source(const float* __restrict__ proj) {
    int idx = blockIdx.x * 256 + threadIdx.x;  // BATCH*D
    int b = idx >> 10, d = idx & (D - 1);
    float2 src = make_float2(proj[b * 2 * D + d], proj[b * 2 * D + D + d]);
    g_S2[idx] = cmulf(g_opf[d], src);
}

// t[b,i] = sum_j M[i,j] * S2[b,j] ; one block per i, 128 thr
__global__ void k_tsmall() {
    int i = blockIdx.x;
    int tid = threadIdx.x;
    float2 part[BATCH];
#pragma unroll
    for (int b = 0; b < BATCH; ++b) part[b] = make_float2(0.f, 0.f);
    for (int j = tid; j < D; j += 128) {
        float2 m = g_M[(size_t)i * D + j];
#pragma unroll
        for (int b = 0; b < BATCH; ++b) {
            float2 s = g_S2[b * D + j];
            part[b].x = fmaf(m.x, s.x, fmaf(-m.y, s.y, part[b].x));
            part[b].y = fmaf(m.x, s.y, fmaf(m.y, s.x, part[b].y));
        }
    }
    __shared__ float2 red[BATCH][128];
#pragma unroll
    for (int b = 0; b < BATCH; ++b) red[b][tid] = part[b];
    __syncthreads();
    if (tid < BATCH) {
        float2 s = make_float2(0.f, 0.f);
#pragma unroll 8
        for (int j = 0; j < 128; ++j) {
            s.x += red[tid][j].x;
            s.y += red[tid][j].y;
        }
        g_t[tid * D + i] = s;
    }
}

// pack [h|x] into complex HX (TB x 2D)
__global__ void k_pack(const float* __restrict__ hre, const float* __restrict__ him,
                       const float* __restrict__ xre, const float* __restrict__ xim) {
    int idx = blockIdx.x * 256 + threadIdx.x;  // TB*2D
    int n = idx >> 11, k = idx & (2 * D - 1);
    float2 v;
    if (k < D)
        v = make_float2(hre[n * D + k], him[n * D + k]);
    else
        v = make_float2(xre[n * D + k - D], xim[n * D + k - D]);
    g_HX[idx] = v;
}

// out planes: re/im of C + t[batch]
__global__ void k_epi(float* __restrict__ out) {
    int idx = blockIdx.x * 256 + threadIdx.x;  // TB*D
    int n = idx >> 10, i = idx & (D - 1);
    int b = n >> 8;  // spatial = 256
    float2 v = g_C[idx];
    float2 tv = g_t[b * D + i];
    out[idx] = v.x + tv.x;
    out[TB * D + idx] = v.y + tv.y;
}

// ---------------- complex GEMM (FFMA2 / f32x2 inner loop) ----------------
// C[m,n] = sum_k Aop[m,k] * Bop[k,n] (+ Aepi[m,n] if ADDA)
// Aop[m,k] = A[m,k] * (SCALEA ? ascale[k] : 1)
// Bop[k,n] = TRANSB ? (CONJB ? conj(B[n,k]) : B[n,k]) : B[k,n]
// Tile 128x64xK8, 256 threads, 8x4 complex per thread (row-pair packed),
// A stored in smem as de-interleaved re/im planes for packed double2 loads.
#define AW 132  // padded plane width (floats): conflict-free staging stores

template <bool TRANSB, bool CONJB, bool ADDA, bool SCALEA>
__global__ void __launch_bounds__(256, 1)
cgemm_k(const float2* __restrict__ A, int lda, const float2* __restrict__ B, int ldb,
        float2* __restrict__ C, int ldc, int K, const float2* __restrict__ ascale,
        const float2* __restrict__ Aepi) {
    __shared__ __align__(16) float AsRe[2][8][AW];
    __shared__ __align__(16) float AsIm[2][8][AW];
    __shared__ __align__(16) float2 Bs[2][8][64];

    const int tid = threadIdx.x;
    const int m0 = blockIdx.x * 128;
    const int n0 = blockIdx.y * 64;
    const int ty = tid >> 4;   // 0..15: rows ty*8 .. ty*8+7
    const int txx = tid & 15;  // cols txx + 16*c

    float2 aS[2][2];  // staged A (scaled)
    float2 bS[2];     // staged B (conj applied)

    auto loadA = [&](int kt) {
#pragma unroll
        for (int i = 0; i < 2; ++i) {
            int idx = tid + 256 * i;
            int row = idx >> 2;
            int kk = (idx & 3) << 1;
            float4 v = *reinterpret_cast<const float4*>(
                A + (size_t)(m0 + row) * lda + kt + kk);
            float2 a0 = make_float2(v.x, v.y);
            float2 a1 = make_float2(v.z, v.w);
            if (SCALEA) {
                a0 = cmulf(a0, ascale[kt + kk]);
                a1 = cmulf(a1, ascale[kt + kk + 1]);
            }
            aS[i][0] = a0;
            aS[i][1] = a1;
        }
    };
    auto storeA = [&](int buf) {
#pragma unroll
        for (int i = 0; i < 2; ++i) {
            int idx = tid + 256 * i;
            int row = idx >> 2;
            int kk = (idx & 3) << 1;
            AsRe[buf][kk][row]     = aS[i][0].x;
            AsIm[buf][kk][row]     = aS[i][0].y;
            AsRe[buf][kk + 1][row] = aS[i][1].x;
            AsIm[buf][kk + 1][row] = aS[i][1].y;
        }
    };
    auto loadB = [&](int kt) {
        if (TRANSB) {
            int col = tid >> 2;
            int kk = (tid & 3) << 1;
            float4 v = *reinterpret_cast<const float4*>(
                B + (size_t)(n0 + col) * ldb + kt + kk);
            bS[0] = make_float2(v.x, CONJB ? -v.y : v.y);
            bS[1] = make_float2(v.z, CONJB ? -v.w : v.w);
        } else {
            int kk = tid >> 5;
            int col = (tid & 31) << 1;
            float4 v = *reinterpret_cast<const float4*>(
                B + (size_t)(kt + kk) * ldb + n0 + col);
            bS[0] = make_float2(v.x, v.y);
            bS[1] = make_float2(v.z, v.w);
        }
    };
    auto storeB = [&](int buf) {
        if (TRANSB) {
            int col = tid >> 2;
            int kk = (tid & 3) << 1;
            Bs[buf][kk][col] = bS[0];
            Bs[buf][kk + 1][col] = bS[1];
        } else {
            int kk = tid >> 5;
            int col = (tid & 31) << 1;
            Bs[buf][kk][col] = bS[0];
            Bs[buf][kk][col + 1] = bS[1];
        }
    };

    ull accR[4][4], accI[4][4];
    const ull ZERO = dup2(0.f);
#pragma unroll
    for (int p = 0; p < 4; ++p)
#pragma unroll
        for (int c = 0; c < 4; ++c) { accR[p][c] = ZERO; accI[p][c] = ZERO; }

    const ull NEG1 = dup2(-1.f);
    const int ntiles = K >> 3;
    loadA(0);
    loadB(0);
    storeA(0);
    storeB(0);
    __syncthreads();

    for (int t = 0; t < ntiles; ++t) {
        int cur = t & 1;
        if (t + 1 < ntiles) {
            loadA((t + 1) << 3);
            loadB((t + 1) << 3);
        }
#pragma unroll
        for (int k = 0; k < 8; ++k) {
            double2 r01 = *reinterpret_cast<const double2*>(&AsRe[cur][k][ty * 8]);
            double2 r23 = *reinterpret_cast<const double2*>(&AsRe[cur][k][ty * 8 + 4]);
            double2 i01 = *reinterpret_cast<const double2*>(&AsIm[cur][k][ty * 8]);
            double2 i23 = *reinterpret_cast<const double2*>(&AsIm[cur][k][ty * 8 + 4]);
            ull ar[4] = {d2l(r01.x), d2l(r01.y), d2l(r23.x), d2l(r23.y)};
            ull ai[4] = {d2l(i01.x), d2l(i01.y), d2l(i23.x), d2l(i23.y)};
            ull nai[4];
#pragma unroll
            for (int p = 0; p < 4; ++p) nai[p] = fmul2(ai[p], NEG1);
#pragma unroll
            for (int c = 0; c < 4; ++c) {
                float2 b = Bs[cur][k][txx + 16 * c];
                ull br2 = dup2(b.x);
                ull bi2 = dup2(b.y);
#pragma unroll
                for (int p = 0; p < 4; ++p) {
                    accR[p][c] = ffma2(ar[p], br2, accR[p][c]);
                    accR[p][c] = ffma2(nai[p], bi2, accR[p][c]);
                    accI[p][c] = ffma2(ar[p], bi2, accI[p][c]);
                    accI[p][c] = ffma2(ai[p], br2, accI[p][c]);
                }
            }
        }
        if (t + 1 < ntiles) {
            storeA(cur ^ 1);
            storeB(cur ^ 1);
        }
        __syncthreads();
    }

#pragma unroll
    for (int p = 0; p < 4; ++p) {
        int gi = m0 + ty * 8 + 2 * p;
#pragma unroll
        for (int c = 0; c < 4; ++c) {
            int gj = n0 + txx + 16 * c;
            float re0, re1, im0, im1;
            unpack2(accR[p][c], re0, re1);
            unpack2(accI[p][c], im0, im1);
            float2 v0 = make_float2(re0, im0);
            float2 v1 = make_float2(re1, im1);
            if (ADDA) {
                float2 e0 = Aepi[(size_t)gi * ldc + gj];
                float2 e1 = Aepi[(size_t)(gi + 1) * ldc + gj];
                v0.x += e0.x; v0.y += e0.y;
                v1.x += e1.x; v1.y += e1.y;
            }
            C[(size_t)gi * ldc + gj] = v0;
            C[(size_t)(gi + 1) * ldc + gj] = v1;
        }
    }
}

// ---------------- host orchestration ----------------
static float2* symf2(const void* s) {
    void* p = nullptr;
    cudaGetSymbolAddress(&p, s);
    return (float2*)p;
}
static float* symf(const void* s) {
    void* p = nullptr;
    cudaGetSymbolAddress(&p, s);
    return (float*)p;
}

static void cayley(const float* re, const float* im, float2* SA, float2* SP, float2* SP2,
                   float2* ACCa, float2* ACCb, float2* OUT) {
    k_buildA<<<D * D / 256, 256>>>(SA, re, im);
    dim3 g(D / 128, D / 64);
    // P = A^2
    cgemm_k<false, false, false, false><<<g, 256>>>(SA, D, SA, D, SP, D, D, nullptr, nullptr);
    // ACC = (I+A)^2
    k_g0<<<D * D / 256, 256>>>(ACCa, SA, SP);
    float2* acc = ACCa;
    float2* accN = ACCb;
    float2* p = SP;
    float2* pN = SP2;
    for (int i = 0; i < 5; ++i) {
        float2* dst = (i == 4) ? OUT : accN;
        // dst = ACC*P + ACC   (== ACC*(I+P))
        cgemm_k<false, false, true, false><<<g, 256>>>(acc, D, p, D, dst, D, D, nullptr, acc);
        if (i < 4) {
            cgemm_k<false, false, false, false><<<g, 256>>>(p, D, p, D, pN, D, D, nullptr, nullptr);
            float2* tp = p; p = pN; pN = tp;
        }
        accN = acc;
        acc = dst;
    }
}

extern "C" void kernel_launch(void* const* d_in, const int* in_sizes, int n_in,
                              void* d_out, int out_size) {
    const float* h_re   = (const float*)d_in[0];
    const float* h_im   = (const float*)d_in[1];
    const float* x_re   = (const float*)d_in[2];
    const float* x_im   = (const float*)d_in[3];
    const float* xg_re  = (const float*)d_in[4];
    const float* xg_im  = (const float*)d_in[5];
    const float* fl_re  = (const float*)d_in[6];
    const float* fl_im  = (const float*)d_in[7];
    const float* dt     = (const float*)d_in[8];
    const float* u_re   = (const float*)d_in[9];
    const float* u_im   = (const float*)d_in[10];
    const float* v_re   = (const float*)d_in[11];
    const float* v_im   = (const float*)d_in[12];
    const float* lsig   = (const float*)d_in[13];
    const float* dec_re = (const float*)d_in[14];
    const float* dec_im = (const float*)d_in[15];
    const float* mix_w  = (const float*)d_in[16];
    const float* mix_b  = (const float*)d_in[17];
    const float* proj_w = (const float*)d_in[18];
    const float* proj_b = (const float*)d_in[19];
    const float* ld_    = (const float*)d_in[20];
    const float* lf_    = (const float*)d_in[21];
    const float* law_re = (const float*)d_in[22];
    const float* law_im = (const float*)d_in[23];
    float* out = (float*)d_out;

    float2* SA   = symf2(g_SA);
    float2* SP   = symf2(g_SP);
    float2* SP2  = symf2(g_SP2);
    float2* ACCa = symf2(g_ACCa);
    float2* ACCb = symf2(g_ACCb);
    float2* U    = symf2(g_U);
    float2* V    = symf2(g_V);
    float2* Mm   = symf2(g_M);
    float2* Minv = symf2(g_Minv);
    float2* W    = symf2(g_W);
    float2* HX   = symf2(g_HX);
    float2* Cc   = symf2(g_C);
    float2* sd   = symf2(g_s);
    float2* sinv = symf2(g_sinv);
    float2* opd  = symf2(g_opd);
    float2* opf  = symf2(g_opf);
    float*  xm   = symf(g_xm);
    float*  fre  = symf(g_fre);
    float*  fim  = symf(g_fim);
    float*  proj = symf(g_proj);

    // Cayley transforms
    cayley(u_re, u_im, SA, SP, SP2, ACCa, ACCb, U);
    cayley(v_re, v_im, SA, SP, SP2, ACCa, ACCb, V);

    // scales + transition operators
    k_scales<<<4, 256>>>(lsig);
    k_ops<<<4, 256>>>(ld_, lf_, law_re, law_im, dt);

    dim3 gdd(D / 128, D / 64);
    // M = (U * s) V^H     [A=U scaled by s along k, B=V trans+conj]
    cgemm_k<true, true, false, true><<<gdd, 256>>>(U, D, V, D, Mm, D, D, sd, nullptr);
    // M_inv = (V * s^-1) U^H
    cgemm_k<true, true, false, true><<<gdd, 256>>>(V, D, U, D, Minv, D, D, sinv, nullptr);
    // W1 = (M * op_decay_cols) @ M_inv ; W2 = (M * op_forcing_cols) @ M_inv
    cgemm_k<false, false, false, true><<<gdd, 256>>>(Mm, D, Minv, D, W, 2 * D, D, opd, nullptr);
    cgemm_k<false, false, false, true><<<gdd, 256>>>(Mm, D, Minv, D, W + D, 2 * D, D, opf, nullptr);

    // flux tracker chain
    k_smallgemm<<<2 * D, 128>>>(xg_re, xg_im, mix_w, mix_b, xm);
    k_flux<<<BATCH * D / 256, 256>>>(fl_re, fl_im, dec_re, dec_im, xm, out);
    k_smallgemm<<<2 * D, 128>>>(fre, fim, proj_w, proj_b, proj);
    k_source<<<BATCH * D / 256, 256>>>(proj);
    k_tsmall<<<D, 128>>>();

    // main pass: C = [h|x] @ [W1|W2]^T
    k_pack<<<TB * 2 * D / 256, 256>>>(h_re, h_im, x_re, x_im);
    dim3 gmain(TB / 128, D / 64);
    cgemm_k<true, false, false, false><<<gmain, 256>>>(HX, 2 * D, W, 2 * D, Cc, D, 2 * D,
                                                       nullptr, nullptr);
    k_epi<<<TB * D / 256, 256>>>(out);

    (void)in_sizes; (void)n_in; (void)out_size;
}

// round 9
// speedup vs baseline: 2.4616x; 2.0907x over previous
#include <cuda_runtime.h>
#include <cuda_bf16.h>
#include <math.h>
#include <stdint.h>

#define D 1024
#define TB 4096
#define BATCH 16
typedef unsigned long long ull;

// ---------- scratch: plane-row format, row i = [re(Kc) | im(Kc)] ----------
__device__ __align__(16) float g_Ask[D * 2 * D];
__device__ __align__(16) float g_pA [D * 2 * D];
__device__ __align__(16) float g_pB [D * 2 * D];
__device__ __align__(16) float g_a0 [D * 2 * D];
__device__ __align__(16) float g_a1 [D * 2 * D];
__device__ __align__(16) float g_UV0[D * 2 * D];
__device__ __align__(16) float g_UV1[D * 2 * D];
__device__ __align__(16) float g_Mpl[D * 2 * D];
__device__ __align__(16) float g_X  [D * 2 * D];
__device__ __align__(16) float g_Us [D * 2 * D];
__device__ __align__(16) float g_Usi[D * 2 * D];
__device__ __align__(16) float g_Md [D * 2 * D];
__device__ __align__(16) float g_Mf [D * 2 * D];
__device__ __align__(16) float g_W  [D * 4 * D];
__device__ __align__(16) float g_HX [TB * 4 * D];  // 4096 x 4096
__device__ __align__(16) float g_Cre[TB * D];
__device__ __align__(16) float g_Cim[TB * D];

__device__ float2 g_s[D];
__device__ float2 g_sinv[D];
__device__ float2 g_opd[D];
__device__ float2 g_opf[D];
__device__ float  g_xm  [BATCH * 2 * D];
__device__ float  g_fre [BATCH * D];
__device__ float  g_fim [BATCH * D];
__device__ float  g_proj[BATCH * 2 * D];
__device__ float2 g_Sv  [BATCH * D];
__device__ float2 g_t   [BATCH * D];

__device__ __forceinline__ float2 cmulf(float2 a, float2 b) {
    return make_float2(fmaf(a.x, b.x, -a.y * b.y), fmaf(a.x, b.y, a.y * b.x));
}

__device__ __forceinline__ uint32_t smem_u32(const void* p) {
    uint32_t a;
    asm("{ .reg .u64 t; cvta.to.shared.u64 t, %1; cvt.u32.u64 %0, t; }" : "=r"(a) : "l"(p));
    return a;
}

// split 2 floats into packed bf16x2 hi & lo
__device__ __forceinline__ void bsplit(float a, float b, uint32_t& h, uint32_t& l) {
    __nv_bfloat16 ha = __float2bfloat16_rn(a), hb = __float2bfloat16_rn(b);
    __nv_bfloat16 la = __float2bfloat16_rn(a - __bfloat162float(ha));
    __nv_bfloat16 lb = __float2bfloat16_rn(b - __bfloat162float(hb));
    __nv_bfloat162 H(ha, hb), L(la, lb);
    h = reinterpret_cast<uint32_t&>(H);
    l = reinterpret_cast<uint32_t&>(L);
}

// 8 floats (scaled) -> hi uint4 + lo uint4 (8 bf16 each)
__device__ __forceinline__ void cvt8(float4 u, float4 v, float s, uint4& H, uint4& L) {
    uint32_t h0, h1, h2, h3, l0, l1, l2, l3;
    bsplit(u.x * s, u.y * s, h0, l0);
    bsplit(u.z * s, u.w * s, h1, l1);
    bsplit(v.x * s, v.y * s, h2, l2);
    bsplit(v.z * s, v.w * s, h3, l3);
    H = make_uint4(h0, h1, h2, h3);
    L = make_uint4(l0, l1, l2, l3);
}

__device__ __forceinline__ void ldm_x4(uint32_t* r, uint32_t addr) {
    asm volatile("ldmatrix.sync.aligned.m8n8.x4.shared.b16 {%0,%1,%2,%3}, [%4];"
                 : "=r"(r[0]), "=r"(r[1]), "=r"(r[2]), "=r"(r[3]) : "r"(addr));
}
__device__ __forceinline__ void ldm_x2(uint32_t* r, uint32_t addr) {
    asm volatile("ldmatrix.sync.aligned.m8n8.x2.shared.b16 {%0,%1}, [%2];"
                 : "=r"(r[0]), "=r"(r[1]) : "r"(addr));
}
__device__ __forceinline__ void mma16816(float* d, const uint32_t* a, const uint32_t* b) {
    asm volatile(
        "mma.sync.aligned.m16n8k16.row.col.f32.bf16.bf16.f32 "
        "{%0,%1,%2,%3}, {%4,%5,%6,%7}, {%8,%9}, {%0,%1,%2,%3};"
        : "+f"(d[0]), "+f"(d[1]), "+f"(d[2]), "+f"(d[3])
        : "r"(a[0]), "r"(a[1]), "r"(a[2]), "r"(a[3]), "r"(b[0]), "r"(b[1]));
}

// swizzled smem offset: tile row-major, 64B/row (32 bf16), 16B chunks XOR-swizzled
__device__ __forceinline__ uint32_t swz(int row, int chunk) {
    return (uint32_t)(row * 64 + ((chunk ^ ((row >> 1) & 3)) << 4));
}

// ---------- HMMA GEMM ----------
// C[m,n'] = sum over K2=2Kc of Arow[m,q] * Bop[n',q]; complex embedded,
// 3-term bf16 split (AhBh + AlBh + AhBl). Block 128x128, 8 warps 64x32.
struct GP {
    const float* A;   // Mrows x 2Kc fp32
    const float* B;   // Nc(=D) x 2Kc fp32
    float* Cre; float* Cim; int ldc;
    const float* Ere; const float* Eim; int lde;
    float sgnr, sgni;
};

#define A_HI 0
#define A_LO 8192
#define B_HI 16384
#define B_LO 24576

__global__ void __launch_bounds__(256, 1) hmma_gemm(GP p, int Kc) {
    __shared__ __align__(128) uint8_t sm[32768];
    const uint32_t sb = smem_u32(sm);
    const int tid = threadIdx.x;
    const int lane = tid & 31;
    const int wid = tid >> 5;
    const int wm = (wid & 1) * 64;
    const int wn = (wid >> 1) * 32;
    const int K2 = 2 * Kc;
    const int Nc = D;
    const int m0 = blockIdx.x * 128;
    const int n0 = blockIdx.y * 128;
    const int isim_n = (n0 >= Nc);
    const int nsrc0 = n0 - (isim_n ? Nc : 0);
    const int T = K2 >> 5;

    float acc[4][4][4];
#pragma unroll
    for (int i = 0; i < 4; ++i)
#pragma unroll
        for (int j = 0; j < 4; ++j)
#pragma unroll
            for (int k = 0; k < 4; ++k) acc[i][j][k] = 0.f;

    float4 sa[2][2], sbv[2][2];

    auto stage = [&](int t) {
        const int kb = t << 5;
        const int isim_k = (kb >= Kc);
        const int qoff = kb - (isim_k ? Kc : 0);
        const int pl = isim_n ? (1 - isim_k) : isim_k;
        const int bcol = pl * Kc + qoff;
#pragma unroll
        for (int i = 0; i < 2; ++i) {
            int task = tid + (i << 8);
            int row = task >> 2, c = task & 3;
            const float* ap = p.A + (size_t)(m0 + row) * K2 + kb + c * 8;
            sa[i][0] = *reinterpret_cast<const float4*>(ap);
            sa[i][1] = *reinterpret_cast<const float4*>(ap + 4);
            const float* bp = p.B + (size_t)(nsrc0 + row) * K2 + bcol + c * 8;
            sbv[i][0] = *reinterpret_cast<const float4*>(bp);
            sbv[i][1] = *reinterpret_cast<const float4*>(bp + 4);
        }
    };
    auto sts = [&](int t) {
        const int kb = t << 5;
        const int isim_k = (kb >= Kc);
        const int pl = isim_n ? (1 - isim_k) : isim_k;
        const float sg = ((!isim_n && isim_k) ? -1.f : 1.f) * (pl ? p.sgni : p.sgnr);
#pragma unroll
        for (int i = 0; i < 2; ++i) {
            int task = tid + (i << 8);
            int row = task >> 2, c = task & 3;
            uint32_t off = swz(row, c);
            uint4 H, L;
            cvt8(sa[i][0], sa[i][1], 1.f, H, L);
            *reinterpret_cast<uint4*>(sm + A_HI + off) = H;
            *reinterpret_cast<uint4*>(sm + A_LO + off) = L;
            cvt8(sbv[i][0], sbv[i][1], sg, H, L);
            *reinterpret_cast<uint4*>(sm + B_HI + off) = H;
            *reinterpret_cast<uint4*>(sm + B_LO + off) = L;
        }
    };

    stage(0);
    for (int t = 0; t < T; ++t) {
        sts(t);
        __syncthreads();
        if (t + 1 < T) stage(t + 1);
#pragma unroll
        for (int k16 = 0; k16 < 2; ++k16) {
            uint32_t ah[4][4], al[4][4], bh[4][2], bl[4][2];
            int amat = lane >> 3;
            int arow_off = (lane & 7) + ((amat & 1) << 3);
            int achk = 2 * k16 + (amat >> 1);
#pragma unroll
            for (int mf = 0; mf < 4; ++mf) {
                int r = wm + mf * 16 + arow_off;
                uint32_t off = swz(r, achk);
                ldm_x4(ah[mf], sb + A_HI + off);
                ldm_x4(al[mf], sb + A_LO + off);
            }
            // B: smem holds Bop[n][k] (N x K row-major) == col-major B -> NON-trans ldmatrix
            int bmat = (lane & 15) >> 3;
            int brow_off = lane & 7;
            int bchk = 2 * k16 + bmat;
#pragma unroll
            for (int nf = 0; nf < 4; ++nf) {
                int r = wn + nf * 8 + brow_off;
                uint32_t off = swz(r, bchk);
                ldm_x2(bh[nf], sb + B_HI + off);
                ldm_x2(bl[nf], sb + B_LO + off);
            }
#pragma unroll
            for (int mf = 0; mf < 4; ++mf)
#pragma unroll
                for (int nf = 0; nf < 4; ++nf) {
                    mma16816(acc[mf][nf], ah[mf], bh[nf]);
                    mma16816(acc[mf][nf], al[mf], bh[nf]);
                    mma16816(acc[mf][nf], ah[mf], bl[nf]);
                }
        }
        __syncthreads();
    }

    float* op = isim_n ? p.Cim : p.Cre;
    const float* ep = isim_n ? p.Eim : p.Ere;
#pragma unroll
    for (int mf = 0; mf < 4; ++mf) {
        int r0 = m0 + wm + mf * 16 + (lane >> 2);
#pragma unroll
        for (int nf = 0; nf < 4; ++nf) {
            int col = nsrc0 + wn + nf * 8 + (lane & 3) * 2;
            float2 v0 = make_float2(acc[mf][nf][0], acc[mf][nf][1]);
            float2 v1 = make_float2(acc[mf][nf][2], acc[mf][nf][3]);
            if (p.Ere) {
                v0.x += ep[(size_t)r0 * p.lde + col];
                v0.y += ep[(size_t)r0 * p.lde + col + 1];
                v1.x += ep[(size_t)(r0 + 8) * p.lde + col];
                v1.y += ep[(size_t)(r0 + 8) * p.lde + col + 1];
            }
            *reinterpret_cast<float2*>(&op[(size_t)r0 * p.ldc + col]) = v0;
            *reinterpret_cast<float2*>(&op[(size_t)(r0 + 8) * p.ldc + col]) = v1;
        }
    }
}

// ---------- small kernels ----------
__global__ void k_buildA(float* __restrict__ A, const float* __restrict__ re,
                         const float* __restrict__ im) {
    int idx = blockIdx.x * 256 + threadIdx.x;
    int i = idx >> 10, j = idx & (D - 1);
    A[(size_t)i * 2048 + j] = 0.5f * (re[i * D + j] - re[j * D + i]);
    A[(size_t)i * 2048 + D + j] = 0.5f * (im[i * D + j] + im[j * D + i]);
}

__global__ void k_g0(float* __restrict__ ACC, const float* __restrict__ A,
                     const float* __restrict__ P) {
    int idx = blockIdx.x * 256 + threadIdx.x;
    int i = idx >> 10, j = idx & (D - 1);
    size_t rr = (size_t)i * 2048 + j, ri = rr + D;
    float dgl = (i == j) ? 1.f : 0.f;
    ACC[rr] = dgl + 2.f * A[rr] + P[rr];
    ACC[ri] = 2.f * A[ri] + P[ri];
}

__global__ void k_colscale(float* __restrict__ dst, const float* __restrict__ src,
                           const float2* __restrict__ c) {
    int idx = blockIdx.x * 256 + threadIdx.x;
    int i = idx >> 10, j = idx & (D - 1);
    size_t rr = (size_t)i * 2048 + j, ri = rr + D;
    float sr = src[rr], si = src[ri];
    float2 cc = c[j];
    dst[rr] = sr * cc.x - si * cc.y;
    dst[ri] = sr * cc.y + si * cc.x;
}

__global__ void k_scales(const float* __restrict__ ls) {
    int d = blockIdx.x * 256 + threadIdx.x;
    if (d >= D) return;
    g_s[d] = make_float2(expf(ls[d]), 0.f);
    g_sinv[d] = make_float2(expf(-ls[d]), 0.f);
}

__global__ void k_ops(const float* __restrict__ ld_, const float* __restrict__ lf_,
                      const float* __restrict__ lawre, const float* __restrict__ lawim,
                      const float* __restrict__ dtp) {
    int d = blockIdx.x * 256 + threadIdx.x;
    if (d >= D) return;
    float dtv = dtp[0];
    float lre = -expf(ld_[d]) + lawre[d];
    float lim = lf_[d] + lawim[d];
    float z = -lre;
    float sp = (z > 0.f) ? (z + log1pf(expf(-z))) : log1pf(expf(z));
    float2 Z = make_float2(-sp * dtv, lim * dtv);
    float ex = expf(Z.x);
    float sy, cy;
    sincosf(Z.y, &sy, &cy);
    float2 ez = make_float2(ex * cy, ex * sy);
    g_opd[d] = ez;
    float az2 = Z.x * Z.x + Z.y * Z.y;
    float2 phi;
    if (sqrtf(az2) < 1e-4f) {
        float2 z2 = cmulf(Z, Z);
        phi = make_float2(1.f + 0.5f * Z.x + z2.x * (1.f / 6.f), 0.5f * Z.y + z2.y * (1.f / 6.f));
    } else {
        float2 num = make_float2(ez.x - 1.f, ez.y);
        float inv = 1.f / az2;
        phi = make_float2((num.x * Z.x + num.y * Z.y) * inv, (num.y * Z.x - num.x * Z.y) * inv);
    }
    g_opf[d] = make_float2(phi.x * dtv, phi.y * dtv);
}

__global__ void k_smallgemm(const float* __restrict__ lo, const float* __restrict__ hi,
                            const float* __restrict__ w, const float* __restrict__ bias,
                            float* __restrict__ outp) {
    int o = blockIdx.x;
    int tid = threadIdx.x;
    float part[BATCH];
#pragma unroll
    for (int b = 0; b < BATCH; ++b) part[b] = 0.f;
    const float* wr = w + (size_t)o * (2 * D);
    for (int k = tid; k < 2 * D; k += 128) {
        float wv = wr[k];
        const float* src = (k < D) ? (lo + k) : (hi + (k - D));
#pragma unroll
        for (int b = 0; b < BATCH; ++b) part[b] = fmaf(src[b * D], wv, part[b]);
    }
    __shared__ float red[BATCH][128];
#pragma unroll
    for (int b = 0; b < BATCH; ++b) red[b][tid] = part[b];
    __syncthreads();
    if (tid < BATCH) {
        float sv = bias[o];
#pragma unroll 8
        for (int j = 0; j < 128; ++j) sv += red[tid][j];
        outp[tid * 2 * D + o] = sv;
    }
}

__global__ void k_flux(const float* __restrict__ fre, const float* __restrict__ fim,
                       const float* __restrict__ dre, const float* __restrict__ dim_,
                       const float* __restrict__ xm, float* __restrict__ out) {
    int idx = blockIdx.x * 256 + threadIdx.x;
    int b = idx >> 10, d = idx & (D - 1);
    float2 dec = make_float2(1.f / (1.f + expf(-dre[d])), dim_[d]);
    float2 f = make_float2(fre[idx], fim[idx]);
    float2 fn = cmulf(f, dec);
    fn.x += xm[b * 2 * D + d];
    fn.y += xm[b * 2 * D + D + d];
    g_fre[idx] = fn.x;
    g_fim[idx] = fn.y;
    out[2 * TB * D + idx] = fn.x;
    out[2 * TB * D + BATCH * D + idx] = fn.y;
}

__global__ void k_source(const float* __restrict__ proj) {
    int idx = blockIdx.x * 256 + threadIdx.x;
    int b = idx >> 10, d = idx & (D - 1);
    float2 src = make_float2(proj[b * 2 * D + d], proj[b * 2 * D + D + d]);
    g_Sv[idx] = cmulf(g_opf[d], src);
}

__global__ void k_tsmall() {
    int i = blockIdx.x;
    int tid = threadIdx.x;
    float2 part[BATCH];
#pragma unroll
    for (int b = 0; b < BATCH; ++b) part[b] = make_float2(0.f, 0.f);
    for (int j = tid; j < D; j += 128) {
        float2 m = make_float2(g_Mpl[(size_t)i * 2048 + j], g_Mpl[(size_t)i * 2048 + D + j]);
#pragma unroll
        for (int b = 0; b < BATCH; ++b) {
            float2 sv = g_Sv[b * D + j];
            part[b].x = fmaf(m.x, sv.x, fmaf(-m.y, sv.y, part[b].x));
            part[b].y = fmaf(m.x, sv.y, fmaf(m.y, sv.x, part[b].y));
        }
    }
    __shared__ float2 red[BATCH][128];
#pragma unroll
    for (int b = 0; b < BATCH; ++b) red[b][tid] = part[b];
    __syncthreads();
    if (tid < BATCH) {
        float2 sv = make_float2(0.f, 0.f);
#pragma unroll 8
        for (int j = 0; j < 128; ++j) { sv.x += red[tid][j].x; sv.y += red[tid][j].y; }
        g_t[tid * D + i] = sv;
    }
}

// HX row n = [hre | xre | him | xim]
__global__ void k_pack(const float* __restrict__ hre, const float* __restrict__ him,
                       const float* __restrict__ xre, const float* __restrict__ xim) {
    int idx = blockIdx.x * 256 + threadIdx.x;  // TB*D
    int n = idx >> 10, k = idx & (D - 1);
    size_t rb = (size_t)n * 4096;
    g_HX[rb + k] = hre[idx];
    g_HX[rb + D + k] = xre[idx];
    g_HX[rb + 2 * D + k] = him[idx];
    g_HX[rb + 3 * D + k] = xim[idx];
}

__global__ void k_epi(float* __restrict__ out) {
    int idx = blockIdx.x * 256 + threadIdx.x;  // TB*D
    int n = idx >> 10, i = idx & (D - 1);
    int b = n >> 8;
    float2 tv = g_t[b * D + i];
    out[idx] = g_Cre[idx] + tv.x;
    out[TB * D + idx] = g_Cim[idx] + tv.y;
}

// ---------- host ----------
static float* symf(const void* s) {
    void* p = nullptr;
    cudaGetSymbolAddress(&p, s);
    return (float*)p;
}
static float2* symf2(const void* s) {
    void* p = nullptr;
    cudaGetSymbolAddress(&p, s);
    return (float2*)p;
}

static void gemm(const float* A, const float* B, float sr, float si, float* Cre, float* Cim,
                 int ldc, const float* Ere, const float* Eim, int lde, int Kc, int Mrows) {
    GP p;
    p.A = A; p.B = B; p.Cre = Cre; p.Cim = Cim; p.ldc = ldc;
    p.Ere = Ere; p.Eim = Eim; p.lde = lde; p.sgnr = sr; p.sgni = si;
    dim3 g(Mrows / 128, 16, 1);
    hmma_gemm<<<g, 256>>>(p, Kc);
}

static void chain(const float* re, const float* im, float* UV) {
    float* As = symf(g_Ask);
    float* pA = symf(g_pA);
    float* pB = symf(g_pB);
    float* a0 = symf(g_a0);
    float* a1 = symf(g_a1);
    k_buildA<<<4096, 256>>>(As, re, im);
    gemm(As, As, -1.f, 1.f, pA, pA + D, 2048, 0, 0, 0, D, D);          // P2 = A*A
    k_g0<<<4096, 256>>>(a0, As, pA);                                    // ACC0 = (I+A)^2
    gemm(a0, pA, 1.f, -1.f, a1, a1 + D, 2048, a0, a0 + D, 2048, D, D);  // ACC1
    gemm(pA, pA, 1.f, -1.f, pB, pB + D, 2048, 0, 0, 0, D, D);           // P4
    gemm(a1, pB, 1.f, -1.f, a0, a0 + D, 2048, a1, a1 + D, 2048, D, D);  // ACC2
    gemm(pB, pB, 1.f, -1.f, pA, pA + D, 2048, 0, 0, 0, D, D);           // P8
    gemm(a0, pA, 1.f, -1.f, a1, a1 + D, 2048, a0, a0 + D, 2048, D, D);  // ACC3
    gemm(pA, pA, 1.f, -1.f, pB, pB + D, 2048, 0, 0, 0, D, D);           // P16
    gemm(a1, pB, 1.f, -1.f, UV, UV + D, 2048, a1, a1 + D, 2048, D, D);  // UV
}

extern "C" void kernel_launch(void* const* d_in, const int* in_sizes, int n_in,
                              void* d_out, int out_size) {
    const float* h_re = (const float*)d_in[0];
    const float* h_im = (const float*)d_in[1];
    const float* x_re = (const float*)d_in[2];
    const float* x_im = (const float*)d_in[3];
    const float* xg_re = (const float*)d_in[4];
    const float* xg_im = (const float*)d_in[5];
    const float* fl_re = (const float*)d_in[6];
    const float* fl_im = (const float*)d_in[7];
    const float* dt = (const float*)d_in[8];
    const float* u_re = (const float*)d_in[9];
    const float* u_im = (const float*)d_in[10];
    const float* v_re = (const float*)d_in[11];
    const float* v_im = (const float*)d_in[12];
    const float* lsig = (const float*)d_in[13];
    const float* dec_re = (const float*)d_in[14];
    const float* dec_im = (const float*)d_in[15];
    const float* mix_w = (const float*)d_in[16];
    const float* mix_b = (const float*)d_in[17];
    const float* proj_w = (const float*)d_in[18];
    const float* proj_b = (const float*)d_in[19];
    const float* ld_ = (const float*)d_in[20];
    const float* lf_ = (const float*)d_in[21];
    const float* law_re = (const float*)d_in[22];
    const float* law_im = (const float*)d_in[23];
    float* out = (float*)d_out;

    float* UV0 = symf(g_UV0);
    float* UV1 = symf(g_UV1);
    float* Mpl = symf(g_Mpl);
    float* X = symf(g_X);
    float* Us = symf(g_Us);
    float* Usi = symf(g_Usi);
    float* Md = symf(g_Md);
    float* Mf = symf(g_Mf);
    float* W = symf(g_W);
    float* HX = symf(g_HX);
    float* Cre = symf(g_Cre);
    float* Cim = symf(g_Cim);
    float2* sd = symf2(g_s);
    float2* sinv = symf2(g_sinv);
    float2* opd = symf2(g_opd);
    float2* opf = symf2(g_opf);
    float* xm = symf(g_xm);
    float* fre = symf(g_fre);
    float* fim = symf(g_fim);
    float* proj = symf(g_proj);

    chain(u_re, u_im, UV0);  // U
    chain(v_re, v_im, UV1);  // V

    k_scales<<<4, 256>>>(lsig);
    k_ops<<<4, 256>>>(ld_, lf_, law_re, law_im, dt);

    k_colscale<<<4096, 256>>>(Us, UV0, sd);
    k_colscale<<<4096, 256>>>(Usi, UV0, sinv);
    gemm(Us, UV1, 1.f, -1.f, Mpl, Mpl + D, 2048, 0, 0, 0, D, D);   // M = (U s) V^H
    gemm(Usi, UV1, 1.f, -1.f, X, X + D, 2048, 0, 0, 0, D, D);      // X = (U s^-1) V^H
    k_colscale<<<4096, 256>>>(Md, Mpl, opd);
    k_colscale<<<4096, 256>>>(Mf, Mpl, opf);
    // W1 = Md @ Minv (Minv row-read = conj rows of X) ; W row = [W1r|W2r|W1i|W2i]
    gemm(Md, X, 1.f, -1.f, W, W + 2 * D, 4096, 0, 0, 0, D, D);       // W1
    gemm(Mf, X, 1.f, -1.f, W + D, W + 3 * D, 4096, 0, 0, 0, D, D);   // W2

    k_smallgemm<<<2 * D, 128>>>(xg_re, xg_im, mix_w, mix_b, xm);
    k_flux<<<BATCH * D / 256, 256>>>(fl_re, fl_im, dec_re, dec_im, xm, out);
    k_smallgemm<<<2 * D, 128>>>(fre, fim, proj_w, proj_b, proj);
    k_source<<<BATCH * D / 256, 256>>>(proj);
    k_tsmall<<<D, 128>>>();

    k_pack<<<TB * D / 256, 256>>>(h_re, h_im, x_re, x_im);
    gemm(HX, W, 1.f, 1.f, Cre, Cim, D, 0, 0, 0, 2 * D, TB);  // main
    k_epi<<<TB * D / 256, 256>>>(out);

    (void)in_sizes; (void)n_in; (void)out_size;
}